// round 1
// baseline (speedup 1.0000x reference)
#include <cuda_runtime.h>
#include <cuda_bf16.h>

// Problem constants (mirror reference)
#define BN   8
#define NP   2048
#define NC   2
#define DETK 100
#define NT   1024

static __device__ __forceinline__ float stable_sigmoid(float d) {
    // matches softmax([c0,c1])[1] with max-subtraction rounding closely
    return (d >= 0.0f) ? (1.0f / (1.0f + expf(-d)))
                       : (expf(d) / (1.0f + expf(d)));
}

static __device__ __forceinline__ unsigned f2s(float f) {
    unsigned u = __float_as_uint(f);
    return (u & 0x80000000u) ? ~u : (u | 0x80000000u);
}
static __device__ __forceinline__ float s2f(unsigned u) {
    u = (u & 0x80000000u) ? (u & 0x7FFFFFFFu) : ~u;
    return __uint_as_float(u);
}

struct SmemLayout {
    float4              sbox[NP];     // decoded+clipped boxes, ORIGINAL index order (32768 B)
    unsigned long long  skeys[NP];    // sorted keys: [score_sortable:32 | (NP-1-j):32] (16384 B)
    unsigned            cand[64];     // candidate bitmask over SORTED positions
    int                 keep[DETK];   // kept sorted positions, in keep order
    int                 s_cur;
    int                 s_cnt;
};

__global__ __launch_bounds__(NT, 1)
void seas_postprocess_kernel(const float* __restrict__ clss,   // [B,N,2]
                             const float* __restrict__ regs,   // [B,N,4]
                             const float* __restrict__ qlts,   // [B,N,1]
                             const float* __restrict__ props,  // [B,N,4]
                             float* __restrict__ out)          // [3200|800|800|800]
{
    extern __shared__ unsigned char smem_raw[];
    SmemLayout& sm = *reinterpret_cast<SmemLayout*>(smem_raw);

    const int b   = blockIdx.x;
    const int tid = threadIdx.x;

    const float W_IMG = 1344.0f, H_IMG = 800.0f;
    const float NEGF  = -1e30f;
    const float CLIPV = 4.135166556742356f;  // log(1000/16)
    const float NMS_T = 0.4f;

    const float* cls = clss  + (size_t)b * NP * NC;
    const float* reg = regs  + (size_t)b * NP * 4;
    const float* qlt = qlts  + (size_t)b * NP;
    const float* prp = props + (size_t)b * NP * 4;

    // ---- Phase 1: decode, clip, score, build sort keys ----
    #pragma unroll
    for (int j = tid; j < NP; j += NT) {
        float p0 = prp[4*j+0], p1 = prp[4*j+1], p2 = prp[4*j+2], p3 = prp[4*j+3];
        float w  = p2 - p0, h = p3 - p1;
        float cx = p0 + 0.5f * w, cy = p1 + 0.5f * h;

        float dx = reg[4*j+0] * 0.1f;
        float dy = reg[4*j+1] * 0.1f;
        float dw = fminf(reg[4*j+2] * 0.2f, CLIPV);
        float dh = fminf(reg[4*j+3] * 0.2f, CLIPV);

        float pcx = dx * w + cx;
        float pcy = dy * h + cy;
        float pw  = expf(dw) * w;
        float ph  = expf(dh) * h;

        float x1 = pcx - 0.5f * pw, y1 = pcy - 0.5f * ph;
        float x2 = pcx + 0.5f * pw, y2 = pcy + 0.5f * ph;
        x1 = fminf(fmaxf(x1, 0.0f), W_IMG);
        x2 = fminf(fmaxf(x2, 0.0f), W_IMG);
        y1 = fminf(fmaxf(y1, 0.0f), H_IMG);
        y2 = fminf(fmaxf(y2, 0.0f), H_IMG);

        bool small_keep = ((x2 - x1) >= 0.01f) && ((y2 - y1) >= 0.01f);

        float c0 = cls[2*j], c1 = cls[2*j+1];
        float raw = stable_sigmoid(c1 - c0);         // softmax fg prob (C=2)
        bool  score_keep = raw > 0.5f;
        float score = stable_sigmoid(qlt[j]) * raw;  // quality-weighted

        bool valid = small_keep && score_keep;
        float s = valid ? score : NEGF;

        sm.sbox[j]  = make_float4(x1, y1, x2, y2);
        sm.skeys[j] = ((unsigned long long)f2s(s) << 32) | (unsigned)(NP - 1 - j);
    }
    __syncthreads();

    // ---- Phase 2: bitonic sort DESCENDING on 64-bit keys (stable tie-break) ----
    for (int k = 2; k <= NP; k <<= 1) {
        for (int jj = k >> 1; jj > 0; jj >>= 1) {
            #pragma unroll
            for (int idx = tid; idx < NP; idx += NT) {
                int p = idx ^ jj;
                if (p > idx) {
                    bool asc = (idx & k) != 0;   // final pass: descending
                    unsigned long long a = sm.skeys[idx];
                    unsigned long long c = sm.skeys[p];
                    bool sw = asc ? (a > c) : (a < c);
                    if (sw) { sm.skeys[idx] = c; sm.skeys[p] = a; }
                }
            }
            __syncthreads();
        }
    }

    // ---- Phase 3: cache each thread's sorted-position boxes in registers,
    //              build candidate bitmask over sorted positions ----
    unsigned long long key0 = sm.skeys[tid];
    unsigned long long key1 = sm.skeys[tid + NT];
    int o0 = NP - 1 - (int)(unsigned)key0;
    int o1 = NP - 1 - (int)(unsigned)key1;
    float4 bj0 = sm.sbox[o0];
    float4 bj1 = sm.sbox[o1];
    float aj0 = (bj0.z - bj0.x) * (bj0.w - bj0.y);
    float aj1 = (bj1.z - bj1.x) * (bj1.w - bj1.y);

    {
        int w = tid >> 5;
        bool v0 = s2f((unsigned)(key0 >> 32)) > -1e29f;
        bool v1 = s2f((unsigned)(key1 >> 32)) > -1e29f;
        unsigned m0 = __ballot_sync(0xffffffffu, v0);
        unsigned m1 = __ballot_sync(0xffffffffu, v1);
        if ((tid & 31) == 0) { sm.cand[w] = m0; sm.cand[w + 32] = m1; }
    }
    if (tid == 0) { sm.s_cnt = 0; sm.s_cur = -1; }
    __syncthreads();

    // ---- Phase 4: greedy NMS (stop after DETK keeps — they come in score order) ----
    while (true) {
        if (tid == 0) {
            int found = -1;
            #pragma unroll 4
            for (int ww = 0; ww < 64; ++ww) {
                unsigned m = sm.cand[ww];
                if (m) { found = (ww << 5) + __ffs(m) - 1; sm.cand[ww] = m & (m - 1); break; }
            }
            sm.s_cur = found;
            if (found >= 0) { sm.keep[sm.s_cnt] = found; sm.s_cnt = sm.s_cnt + 1; }
        }
        __syncthreads();
        int i   = sm.s_cur;
        int cnt = sm.s_cnt;
        if (i < 0 || cnt >= DETK) break;

        int iorig = NP - 1 - (int)(unsigned)sm.skeys[i];
        float4 bi = sm.sbox[iorig];
        float ai  = (bi.z - bi.x) * (bi.w - bi.y);

        // j = tid
        {
            float iw = fmaxf(fminf(bi.z, bj0.z) - fmaxf(bi.x, bj0.x), 0.0f);
            float ih = fmaxf(fminf(bi.w, bj0.w) - fmaxf(bi.y, bj0.y), 0.0f);
            float inter = iw * ih;
            float iou = inter / (ai + aj0 - inter + 1e-9f);
            unsigned m = __ballot_sync(0xffffffffu, iou > NMS_T);
            if ((tid & 31) == 0 && m) sm.cand[tid >> 5] &= ~m;
        }
        // j = tid + NT
        {
            float iw = fmaxf(fminf(bi.z, bj1.z) - fmaxf(bi.x, bj1.x), 0.0f);
            float ih = fmaxf(fminf(bi.w, bj1.w) - fmaxf(bi.y, bj1.y), 0.0f);
            float inter = iw * ih;
            float iou = inter / (ai + aj1 - inter + 1e-9f);
            unsigned m = __ballot_sync(0xffffffffu, iou > NMS_T);
            if ((tid & 31) == 0 && m) sm.cand[(tid >> 5) + 32] &= ~m;
        }
        __syncthreads();
    }

    // ---- Phase 5: write outputs [boxes|scores|classes|valid] as float32 ----
    if (tid < DETK) {
        int k = tid;
        float4 ob = make_float4(0.f, 0.f, 0.f, 0.f);
        float os = 0.f, oc = 0.f, ov = 0.f;
        if (k < sm.s_cnt) {
            int si = sm.keep[k];
            unsigned long long key = sm.skeys[si];
            int orig = NP - 1 - (int)(unsigned)key;
            ob = sm.sbox[orig];
            os = s2f((unsigned)(key >> 32));
            oc = 1.0f;
            ov = 1.0f;
        }
        float* obp = out + ((size_t)b * DETK + k) * 4;
        obp[0] = ob.x; obp[1] = ob.y; obp[2] = ob.z; obp[3] = ob.w;
        const int SB = BN * DETK * 4;   // 3200
        const int SC = BN * DETK;       // 800
        out[SB +          b * DETK + k] = os;
        out[SB + SC +     b * DETK + k] = oc;
        out[SB + 2 * SC + b * DETK + k] = ov;
    }
}

extern "C" void kernel_launch(void* const* d_in, const int* in_sizes, int n_in,
                              void* d_out, int out_size) {
    const float* clss  = (const float*)d_in[0];  // [8,2048,2]
    const float* regs  = (const float*)d_in[1];  // [8,2048,4]
    const float* qlts  = (const float*)d_in[2];  // [8,2048,1]
    const float* props = (const float*)d_in[3];  // [8,2048,4]
    float* out = (float*)d_out;

    size_t smem = sizeof(SmemLayout);   // ~49.9 KB -> needs opt-in
    cudaFuncSetAttribute(seas_postprocess_kernel,
                         cudaFuncAttributeMaxDynamicSharedMemorySize, (int)smem);
    seas_postprocess_kernel<<<BN, NT, smem>>>(clss, regs, qlts, props, out);
}

// round 2
// speedup vs baseline: 1.2021x; 1.2021x over previous
#include <cuda_runtime.h>
#include <cuda_bf16.h>

#define BN   8
#define NP   2048
#define DETK 100
#define NT   1024
#define NE   (NP / NT)   // elements per thread = 2

static __device__ __forceinline__ float stable_sigmoid(float d) {
    return (d >= 0.0f) ? (1.0f / (1.0f + expf(-d)))
                       : (expf(d) / (1.0f + expf(d)));
}

static __device__ __forceinline__ unsigned f2s(float f) {
    unsigned u = __float_as_uint(f);
    return (u & 0x80000000u) ? ~u : (u | 0x80000000u);
}
static __device__ __forceinline__ float s2f(unsigned u) {
    u = (u & 0x80000000u) ? (u & 0x7FFFFFFFu) : ~u;
    return __uint_as_float(u);
}

struct Smem {
    float4   sbox[NP];        // decoded+clipped boxes, original index order (32 KB)
    unsigned wkey[32];        // per-warp max score-key
    unsigned widx[32];        // per-warp min index achieving that key
    int      keep[DETK];      // kept original indices, in keep (descending-score) order
    unsigned keepkey[DETK];   // their score keys
    int      sel;             // selected index this iteration (-1 = done)
    int      cnt;             // number of keeps so far
};

__global__ __launch_bounds__(NT, 1)
void seas_postprocess_kernel(const float* __restrict__ clss,   // [B,N,2]
                             const float* __restrict__ regs,   // [B,N,4]
                             const float* __restrict__ qlts,   // [B,N,1]
                             const float* __restrict__ props,  // [B,N,4]
                             float* __restrict__ out)
{
    __shared__ Smem sm;

    const int b   = blockIdx.x;
    const int tid = threadIdx.x;

    const float W_IMG = 1344.0f, H_IMG = 800.0f;
    const float CLIPV = 4.135166556742356f;  // log(1000/16)
    const float NMS_T = 0.4f;

    const float2* cls = (const float2*)(clss  + (size_t)b * NP * 2);
    const float4* reg = (const float4*)(regs  + (size_t)b * NP * 4);
    const float*  qlt =                 qlts  + (size_t)b * NP;
    const float4* prp = (const float4*)(props + (size_t)b * NP * 4);

    float4   myb[NE];
    float    mya[NE];
    unsigned mykey[NE];

    // ---- Phase 1: decode, clip, score; keys + boxes in registers, boxes also in smem ----
    #pragma unroll
    for (int e = 0; e < NE; ++e) {
        int j = e * NT + tid;
        float4 p = prp[j];
        float w  = p.z - p.x, h = p.w - p.y;
        float cx = p.x + 0.5f * w, cy = p.y + 0.5f * h;

        float4 r = reg[j];
        float dx = r.x * 0.1f;
        float dy = r.y * 0.1f;
        float dw = fminf(r.z * 0.2f, CLIPV);
        float dh = fminf(r.w * 0.2f, CLIPV);

        float pcx = dx * w + cx;
        float pcy = dy * h + cy;
        float pw  = expf(dw) * w;
        float ph  = expf(dh) * h;

        float x1 = pcx - 0.5f * pw, y1 = pcy - 0.5f * ph;
        float x2 = pcx + 0.5f * pw, y2 = pcy + 0.5f * ph;
        x1 = fminf(fmaxf(x1, 0.0f), W_IMG);
        x2 = fminf(fmaxf(x2, 0.0f), W_IMG);
        y1 = fminf(fmaxf(y1, 0.0f), H_IMG);
        y2 = fminf(fmaxf(y2, 0.0f), H_IMG);

        bool small_keep = ((x2 - x1) >= 0.01f) && ((y2 - y1) >= 0.01f);

        float2 c = cls[j];
        float raw = stable_sigmoid(c.y - c.x);       // softmax fg prob (C=2)
        bool  score_keep = raw > 0.5f;
        float score = stable_sigmoid(qlt[j]) * raw;  // quality-weighted

        bool valid = small_keep && score_keep;

        float4 box = make_float4(x1, y1, x2, y2);
        sm.sbox[j] = box;
        myb[e]     = box;
        mya[e]     = (x2 - x1) * (y2 - y1);
        mykey[e]   = valid ? f2s(score) : 0u;        // valid <=> key >= 0x80000000
    }
    if (tid == 0) sm.cnt = 0;
    __syncthreads();

    // ---- Phase 2: fused argmax-select + suppress greedy NMS ----
    const int w    = tid >> 5;
    const int lane = tid & 31;

    while (true) {
        // local max over this thread's elements
        unsigned lk = mykey[0];
        #pragma unroll
        for (int e = 1; e < NE; ++e) lk = max(lk, mykey[e]);
        // warp-level hardware reductions
        unsigned gk = __reduce_max_sync(0xffffffffu, lk);
        unsigned li = 0xFFFFFFFFu;
        #pragma unroll
        for (int e = 0; e < NE; ++e)
            if (mykey[e] == gk) li = min(li, (unsigned)(e * NT + tid));
        unsigned gi = __reduce_min_sync(0xffffffffu, li);
        if (lane == 0) { sm.wkey[w] = gk; sm.widx[w] = gi; }
        __syncthreads();

        // warp 0 reduces the 32 warp partials and records the keep
        if (w == 0) {
            unsigned k2 = sm.wkey[lane];
            unsigned i2 = sm.widx[lane];
            unsigned gk2 = __reduce_max_sync(0xffffffffu, k2);
            unsigned cand = (k2 == gk2) ? i2 : 0xFFFFFFFFu;
            unsigned gi2 = __reduce_min_sync(0xffffffffu, cand);
            if (lane == 0) {
                if (gk2 >= 0x80000000u) {
                    int c = sm.cnt;
                    sm.keep[c]    = (int)gi2;
                    sm.keepkey[c] = gk2;
                    sm.cnt        = c + 1;
                    sm.sel        = (int)gi2;
                } else {
                    sm.sel = -1;
                }
            }
        }
        __syncthreads();

        int sel = sm.sel;
        if (sel < 0 || sm.cnt >= DETK) break;

        // suppress: IoU vs kept box (self gets IoU ~1 -> suppressed; explicit check too)
        float4 bi = sm.sbox[sel];
        float  ai = (bi.z - bi.x) * (bi.w - bi.y);
        #pragma unroll
        for (int e = 0; e < NE; ++e) {
            float iw = fmaxf(fminf(bi.z, myb[e].z) - fmaxf(bi.x, myb[e].x), 0.0f);
            float ih = fmaxf(fminf(bi.w, myb[e].w) - fmaxf(bi.y, myb[e].y), 0.0f);
            float inter = iw * ih;
            float iou = inter / (ai + mya[e] - inter + 1e-9f);
            if (iou > NMS_T || (e * NT + tid) == sel) mykey[e] = 0u;
        }
    }

    // ---- Phase 3: write outputs [boxes|scores|classes|valid] as float32 ----
    if (tid < DETK) {
        int k = tid;
        float4 ob = make_float4(0.f, 0.f, 0.f, 0.f);
        float os = 0.f, oc = 0.f, ov = 0.f;
        if (k < sm.cnt) {
            int sel = sm.keep[k];
            ob = sm.sbox[sel];
            os = s2f(sm.keepkey[k]);
            oc = 1.0f;
            ov = 1.0f;
        }
        float* obp = out + ((size_t)b * DETK + k) * 4;
        obp[0] = ob.x; obp[1] = ob.y; obp[2] = ob.z; obp[3] = ob.w;
        const int SB = BN * DETK * 4;   // 3200
        const int SC = BN * DETK;       // 800
        out[SB +          b * DETK + k] = os;
        out[SB + SC +     b * DETK + k] = oc;
        out[SB + 2 * SC + b * DETK + k] = ov;
    }
}

extern "C" void kernel_launch(void* const* d_in, const int* in_sizes, int n_in,
                              void* d_out, int out_size) {
    const float* clss  = (const float*)d_in[0];  // [8,2048,2]
    const float* regs  = (const float*)d_in[1];  // [8,2048,4]
    const float* qlts  = (const float*)d_in[2];  // [8,2048,1]
    const float* props = (const float*)d_in[3];  // [8,2048,4]
    float* out = (float*)d_out;

    seas_postprocess_kernel<<<BN, NT>>>(clss, regs, qlts, props, out);
}